// round 12
// baseline (speedup 1.0000x reference)
#include <cuda_runtime.h>
#include <cuda_fp16.h>
#include <cstdint>
#include <math.h>

#define NB 8
#define NC 32
#define NR 2048
#define NI 64
#define NO 64
#define RT 16                 // r-values per priors block
#define RS 2                  // r-values per pipeline stage (32 KB W slab)
#define NSTAGE (RT / RS)      // 8
#define NSLOT 3               // pipeline ring depth
#define NQ 4                  // R-split quarters in iter_kernel

// dynamic smem layout (bytes): W 3x32KB | x 3x4KB | mbar
#define SMEM_W     0
#define SMEM_X     98304
#define SMEM_MBAR  110592     // full[3] then empty[3], 8B each
#define SMEM_TOTAL 110656

#define STAGE_BYTES (32768 + 4096)

#define TOT (NB * NC * NO)    // 16384

// Scratch (static device globals — no allocation in kernel_launch)
__device__ __half g_ph[NB * NC * NR * NO];      // 67 MB fp16 priors
__device__ float  g_w[TOT];                     // cumulative v (logit weight)
__device__ float  g_pden[NQ * TOT];             // per-quarter softmax denominators
__device__ float  g_pnum[NQ * TOT];             // per-quarter numerators; [0] also = sum_r priors

typedef unsigned long long u64t;

// ---------------------------------------------------------------------------
__device__ __forceinline__ unsigned sptr(const void* p) {
    return (unsigned)__cvta_generic_to_shared(p);
}
__device__ __forceinline__ void mbar_init(unsigned m, unsigned cnt) {
    asm volatile("mbarrier.init.shared.b64 [%0], %1;" :: "r"(m), "r"(cnt) : "memory");
}
__device__ __forceinline__ void mbar_expect(unsigned m, unsigned bytes) {
    asm volatile("mbarrier.arrive.expect_tx.shared.b64 _, [%0], %1;"
                 :: "r"(m), "r"(bytes) : "memory");
}
__device__ __forceinline__ void mbar_arrive(unsigned m) {
    asm volatile("mbarrier.arrive.shared.b64 _, [%0];" :: "r"(m) : "memory");
}
__device__ __forceinline__ void bulk_g2s(unsigned dst, const void* src,
                                         unsigned bytes, unsigned m) {
    asm volatile("cp.async.bulk.shared::cta.global.mbarrier::complete_tx::bytes "
                 "[%0], [%1], %2, [%3];"
                 :: "r"(dst), "l"(src), "r"(bytes), "r"(m) : "memory");
}
__device__ __forceinline__ void mbar_wait(unsigned m, unsigned ph) {
    asm volatile(
        "{\n\t.reg .pred P;\n\t"
        "W1_%=:\n\t"
        "mbarrier.try_wait.parity.acquire.cta.shared::cta.b64 P, [%0], %1, 0x989680;\n\t"
        "@P bra W2_%=;\n\t"
        "bra W1_%=;\n\t"
        "W2_%=:\n\t}"
        :: "r"(m), "r"(ph) : "memory");
}

#define FMA4(A, S, W) { (A).x += (S)*(W).x; (A).y += (S)*(W).y; \
                        (A).z += (S)*(W).z; (A).w += (S)*(W).w; }

// ---------------------------------------------------------------------------
// Kernel 0: zero the accumulators (g_w and quarter-0 of g_pnum).
// ---------------------------------------------------------------------------
__global__ __launch_bounds__(512) void zero_kernel()
{
    int i = blockIdx.x * 512 + threadIdx.x;
    if (i < TOT) { g_w[i] = 0.0f; g_pnum[i] = 0.0f; }
}

// ---------------------------------------------------------------------------
// Kernel 1: priors[b,c,r,o] = sum_i x[b,c,r,i] * W[c,r,i,o], fp16 store.
// Warp-decoupled 3-slot TMA ring. Consumers: 64 threads = rj(2) x bg(2) x
// og(16); each thread computes 4 batches x 4 outputs (G=4/F=4) -> W smem
// read redundancy halves vs the old 2x4 layout: LDS/block-stage 196->131 KB,
// putting the LDS pipe under the DRAM budget. Producer warp = threads 64-95.
// Fuses iteration-0 sum via atomics.
// ---------------------------------------------------------------------------
__global__ __launch_bounds__(96) void priors_kernel(
    const float* __restrict__ x, const float* __restrict__ Wt)
{
    extern __shared__ float sm[];
    float* sW = sm;                          // [NSLOT][RS*NI*NO]
    float* sX = sm + SMEM_X / 4;             // [NSLOT][NB][RS*NI]
    const unsigned smb  = sptr(sm);
    const unsigned mful = smb + SMEM_MBAR;         // full[j] = mful + 8j
    const unsigned memp = smb + SMEM_MBAR + 24;    // empty[j] = memp + 8j

    const int c  = blockIdx.y;
    const int r0 = blockIdx.x * RT;
    const int t  = threadIdx.x;

    if (t == 0) {
#pragma unroll
        for (int j = 0; j < NSLOT; j++) {
            mbar_init(mful + 8 * j, 1);     // completed by expect_tx + TMA
            mbar_init(memp + 8 * j, 2);     // 2 consumer-warp arrivals
        }
    }
    __syncthreads();                        // mbarriers visible to all

    if (t >= 64) {
        // ---------------- producer warp ----------------
        if (t == 64) {
            int eph[NSLOT] = {1, 1, 1};     // first empty-wait passes
            for (int s = 0; s < NSTAGE; s++) {
                const int j = s % NSLOT;
                mbar_wait(memp + 8 * j, eph[j]);
                eph[j] ^= 1;
                const unsigned m = mful + 8 * j;
                mbar_expect(m, STAGE_BYTES);
                bulk_g2s(smb + SMEM_W + j * 32768,
                         Wt + (size_t)(c * NR + r0 + s * RS) * (NI * NO),
                         32768, m);
#pragma unroll
                for (int b = 0; b < NB; b++)
                    bulk_g2s(smb + SMEM_X + j * 4096 + b * (RS * NI * 4),
                             x + (size_t)((b * NC + c) * NR + r0 + s * RS) * NI,
                             RS * NI * 4, m);
            }
        }
        return;
    }

    // ---------------- consumer warps (64 threads) ----------------
    const int rj = t >> 5;            // 0..1
    const int bg = (t >> 4) & 1;      // batches 4bg .. 4bg+3
    const int og = t & 15;            // outputs 4og .. 4og+3
    const int lane0 = ((t & 31) == 0);

    int fph[NSLOT] = {0, 0, 0};
    float4 ms[4];
#pragma unroll
    for (int k = 0; k < 4; k++) ms[k] = make_float4(0.f, 0.f, 0.f, 0.f);

    for (int s = 0; s < NSTAGE; s++) {
        const int j = s % NSLOT;
        mbar_wait(mful + 8 * j, fph[j]);
        fph[j] ^= 1;

        const float* Wb = sW + j * (RS * NI * NO) + rj * (NI * NO);
        const float4* xr[4];
#pragma unroll
        for (int k = 0; k < 4; k++)
            xr[k] = (const float4*)(sX + j * (NB * RS * NI) + ((4 * bg + k) * RS + rj) * NI);

        float4 acc[4];
#pragma unroll
        for (int k = 0; k < 4; k++) acc[k] = make_float4(0.f, 0.f, 0.f, 0.f);

#pragma unroll
        for (int i4 = 0; i4 < NI / 4; i4++) {
            const float4* wrow = (const float4*)(Wb + (i4 * 4) * NO) + og;
            float4 w0 = wrow[0];
            float4 w1 = wrow[16];
            float4 w2 = wrow[32];
            float4 w3 = wrow[48];
#pragma unroll
            for (int k = 0; k < 4; k++) {
                float4 xv = xr[k][i4];
                FMA4(acc[k], xv.x, w0);
                FMA4(acc[k], xv.y, w1);
                FMA4(acc[k], xv.z, w2);
                FMA4(acc[k], xv.w, w3);
            }
        }

        const int r = r0 + s * RS + rj;
#pragma unroll
        for (int k = 0; k < 4; k++) {
            union { uint2 u; __half2 h[2]; } pk;
            pk.h[0] = __floats2half2_rn(acc[k].x, acc[k].y);
            pk.h[1] = __floats2half2_rn(acc[k].z, acc[k].w);
            *(uint2*)(g_ph + (size_t)(((4 * bg + k) * NC + c) * NR + r) * NO + 4 * og) = pk.u;
            ms[k].x += acc[k].x; ms[k].y += acc[k].y;
            ms[k].z += acc[k].z; ms[k].w += acc[k].w;
        }

        __syncwarp();
        if (lane0) mbar_arrive(memp + 8 * j);   // this warp done with slot j
    }

    // iteration-0 fusion: sum_r priors -> g_pnum quarter 0
#pragma unroll
    for (int k = 0; k < 4; k++) {
        float* d = g_pnum + ((4 * bg + k) * NC + c) * NO + 4 * og;
        atomicAdd(d + 0, ms[k].x); atomicAdd(d + 1, ms[k].y);
        atomicAdd(d + 2, ms[k].z); atomicAdd(d + 3, ms[k].w);
    }
}

// ---------------------------------------------------------------------------
// Kernel 2: one routing iteration (branch-free: |w|<=2, |p|<~16 -> exp safe).
// Grid = NQ blocks per (b,c), 512 rows each; partials to scratch quarters.
// ---------------------------------------------------------------------------
__global__ __launch_bounds__(512) void iter_kernel()
{
    const int blk = blockIdx.x;
    const int bc  = blk >> 2;
    const int qq  = blk & 3;
    const int t   = threadIdx.x;
    const int o4  = t & 15;
    const int g   = t >> 4;

    const uint2* p2 = (const uint2*)(g_ph + (size_t)bc * NR * NO)
                      + (size_t)qq * (NR / NQ) * 16;
    const float4 wv = ((const float4*)g_w)[bc * 16 + o4];

    float d0 = 0.f, d1 = 0.f, d2 = 0.f, d3 = 0.f;
    float n0 = 0.f, n1 = 0.f, n2 = 0.f, n3 = 0.f;

#pragma unroll
    for (int k = 0; k < NR / NQ / 32; k++) {      // 16
        uint2 u = p2[(size_t)(g + 32 * k) * 16 + o4];
        float2 pa = __half22float2(*(__half2*)&u.x);
        float2 pb = __half22float2(*(__half2*)&u.y);
        float e;
        e = __expf(pa.x * wv.x); d0 += e; n0 += pa.x * e;
        e = __expf(pa.y * wv.y); d1 += e; n1 += pa.y * e;
        e = __expf(pb.x * wv.z); d2 += e; n2 += pb.x * e;
        e = __expf(pb.y * wv.w); d3 += e; n3 += pb.y * e;
    }

    __shared__ float smr[2][32][64];
    {
        int ob = o4 * 4;
        smr[0][g][ob + 0] = d0; smr[1][g][ob + 0] = n0;
        smr[0][g][ob + 1] = d1; smr[1][g][ob + 1] = n1;
        smr[0][g][ob + 2] = d2; smr[1][g][ob + 2] = n2;
        smr[0][g][ob + 3] = d3; smr[1][g][ob + 3] = n3;
    }
    __syncthreads();

    if (t < 64) {
        float D = 0.f, N = 0.f;
#pragma unroll 8
        for (int g2 = 0; g2 < 32; g2++) {
            D += smr[0][g2][t];
            N += smr[1][g2][t];
        }
        g_pden[qq * TOT + bc * NO + t] = D;
        g_pnum[qq * TOT + bc * NO + t] = N;
    }
}

// ---------------------------------------------------------------------------
// Kernel 3: s -> squash scale -> update w or write out.
// first=1: s = g_pnum[0]/2048 (uniform softmax, fused iteration 0).
// ---------------------------------------------------------------------------
__global__ __launch_bounds__(512) void squash_kernel(float* __restrict__ out,
                                                     int last, int first)
{
    const int t = threadIdx.x;

    float sv[32];
    float acc = 0.f;
#pragma unroll
    for (int q = 0; q < 32; q++) {
        int j = t + 512 * q;
        float s;
        if (first) {
            s = g_pnum[j] * (1.0f / (float)NR);
        } else {
            float D = g_pden[j] + g_pden[TOT + j] + g_pden[2 * TOT + j] + g_pden[3 * TOT + j];
            float N = g_pnum[j] + g_pnum[TOT + j] + g_pnum[2 * TOT + j] + g_pnum[3 * TOT + j];
            s = N / D;
        }
        sv[q] = s;
        acc += s * s;
    }

    __shared__ float red[16];
    __shared__ float s_scale;
#pragma unroll
    for (int off = 16; off > 0; off >>= 1)
        acc += __shfl_xor_sync(0xFFFFFFFFu, acc, off);
    if ((t & 31) == 0) red[t >> 5] = acc;
    __syncthreads();
    if (t < 32) {
        float a = (t < 16) ? red[t] : 0.f;
#pragma unroll
        for (int off = 8; off > 0; off >>= 1)
            a += __shfl_xor_sync(0xFFFFFFFFu, a, off);
        if (t == 0) s_scale = sqrtf(a) / (1.0f + a);
    }
    __syncthreads();
    const float sc = s_scale;

    if (last) {
#pragma unroll
        for (int q = 0; q < 32; q++) out[t + 512 * q] = sv[q] * sc;
    } else {
#pragma unroll
        for (int q = 0; q < 32; q++) g_w[t + 512 * q] += sv[q] * sc;
    }
}

// ---------------------------------------------------------------------------
extern "C" void kernel_launch(void* const* d_in, const int* in_sizes, int n_in,
                              void* d_out, int out_size)
{
    (void)in_sizes; (void)n_in; (void)out_size;
    const float* x  = (const float*)d_in[0];
    const float* Wt = (const float*)d_in[1];
    float* out = (float*)d_out;

    cudaFuncSetAttribute(priors_kernel,
                         cudaFuncAttributeMaxDynamicSharedMemorySize, SMEM_TOTAL);

    zero_kernel<<<32, 512>>>();
    priors_kernel<<<dim3(NR / RT, NC), 96, SMEM_TOTAL>>>(x, Wt);

    squash_kernel<<<1, 512>>>(nullptr, 0, 1);   // w = v0   (iteration 0, fused sum)

    iter_kernel<<<NQ * NB * NC, 512>>>();       // iteration 1
    squash_kernel<<<1, 512>>>(nullptr, 0, 0);   // w = v0 + v1

    iter_kernel<<<NQ * NB * NC, 512>>>();       // iteration 2
    squash_kernel<<<1, 512>>>(out, 1, 0);       // final squash -> output
}

// round 13
// speedup vs baseline: 1.0119x; 1.0119x over previous
#include <cuda_runtime.h>
#include <cuda_fp16.h>
#include <cstdint>
#include <math.h>

#define NB 8
#define NC 32
#define NR 2048
#define NI 64
#define NO 64
#define RT 16                 // r-values per priors block
#define RS 2                  // r-values per pipeline stage (32 KB W slab)
#define NSTAGE (RT / RS)      // 8
#define NSLOT 3               // pipeline ring depth
#define NQ 4                  // R-split quarters in iter_kernel

// priors dynamic smem layout (bytes): W 3x32KB | x 3x4KB | mbar
#define SMEM_W     0
#define SMEM_X     98304
#define SMEM_MBAR  110592     // full[3] then empty[3], 8B each
#define SMEM_TOTAL 110656

#define STAGE_BYTES (32768 + 4096)

// iter dynamic smem: 64KB fp16 tile | 16KB reduce | mbar
#define ITER_TILE   65536
#define ITER_RED    (ITER_TILE)             // float[2][32][64] = 16384 B
#define ITER_MBAR   (ITER_TILE + 16384)
#define ITER_SMEM   (ITER_MBAR + 16)

#define TOT (NB * NC * NO)    // 16384

// Scratch (static device globals — no allocation in kernel_launch)
__device__ __half g_ph[NB * NC * NR * NO];      // 67 MB fp16 priors
__device__ float  g_w[TOT];                     // cumulative v (logit weight)
__device__ float  g_pden[NQ * TOT];             // per-quarter softmax denominators
__device__ float  g_pnum[NQ * TOT];             // per-quarter numerators; [0] also = sum_r priors
__device__ int    g_cnt;                        // last-block counter (reset by last block)

typedef unsigned long long u64t;

// ---------------------------------------------------------------------------
__device__ __forceinline__ unsigned sptr(const void* p) {
    return (unsigned)__cvta_generic_to_shared(p);
}
__device__ __forceinline__ void mbar_init(unsigned m, unsigned cnt) {
    asm volatile("mbarrier.init.shared.b64 [%0], %1;" :: "r"(m), "r"(cnt) : "memory");
}
__device__ __forceinline__ void mbar_expect(unsigned m, unsigned bytes) {
    asm volatile("mbarrier.arrive.expect_tx.shared.b64 _, [%0], %1;"
                 :: "r"(m), "r"(bytes) : "memory");
}
__device__ __forceinline__ void mbar_arrive(unsigned m) {
    asm volatile("mbarrier.arrive.shared.b64 _, [%0];" :: "r"(m) : "memory");
}
__device__ __forceinline__ u64t mkpolicy_evict_first() {
    u64t p;
    asm("createpolicy.fractional.L2::evict_first.b64 %0, 1.0;" : "=l"(p));
    return p;
}
__device__ __forceinline__ void bulk_g2s(unsigned dst, const void* src,
                                         unsigned bytes, unsigned m) {
    asm volatile("cp.async.bulk.shared::cta.global.mbarrier::complete_tx::bytes "
                 "[%0], [%1], %2, [%3];"
                 :: "r"(dst), "l"(src), "r"(bytes), "r"(m) : "memory");
}
__device__ __forceinline__ void bulk_g2s_ef(unsigned dst, const void* src,
                                            unsigned bytes, unsigned m, u64t pol) {
    asm volatile("cp.async.bulk.shared::cta.global.mbarrier::complete_tx::bytes"
                 ".L2::cache_hint [%0], [%1], %2, [%3], %4;"
                 :: "r"(dst), "l"(src), "r"(bytes), "r"(m), "l"(pol) : "memory");
}
__device__ __forceinline__ void mbar_wait(unsigned m, unsigned ph) {
    asm volatile(
        "{\n\t.reg .pred P;\n\t"
        "W1_%=:\n\t"
        "mbarrier.try_wait.parity.acquire.cta.shared::cta.b64 P, [%0], %1, 0x989680;\n\t"
        "@P bra W2_%=;\n\t"
        "bra W1_%=;\n\t"
        "W2_%=:\n\t}"
        :: "r"(m), "r"(ph) : "memory");
}

#define FMA4(A, S, W) { (A).x += (S)*(W).x; (A).y += (S)*(W).y; \
                        (A).z += (S)*(W).z; (A).w += (S)*(W).w; }

// ---------------------------------------------------------------------------
// Kernel 0: zero the accumulators (g_w, quarter-0 of g_pnum, counter).
// ---------------------------------------------------------------------------
__global__ __launch_bounds__(512) void zero_kernel()
{
    int i = blockIdx.x * 512 + threadIdx.x;
    if (i < TOT) { g_w[i] = 0.0f; g_pnum[i] = 0.0f; }
    if (i == 0) g_cnt = 0;
}

// ---------------------------------------------------------------------------
// Kernel 1: priors (round-11 best config, verbatim). Warp-decoupled 3-slot
// TMA ring, evict-first on the W/x stream, iteration-0 sum fused via atomics.
// ---------------------------------------------------------------------------
__global__ __launch_bounds__(160) void priors_kernel(
    const float* __restrict__ x, const float* __restrict__ Wt)
{
    extern __shared__ float sm[];
    float* sW = sm;                          // [NSLOT][RS*NI*NO]
    float* sX = sm + SMEM_X / 4;             // [NSLOT][NB][RS*NI]
    const unsigned smb  = sptr(sm);
    const unsigned mful = smb + SMEM_MBAR;         // full[j] = mful + 8j
    const unsigned memp = smb + SMEM_MBAR + 24;    // empty[j] = memp + 8j

    const int c  = blockIdx.y;
    const int r0 = blockIdx.x * RT;
    const int t  = threadIdx.x;

    if (t == 0) {
#pragma unroll
        for (int j = 0; j < NSLOT; j++) {
            mbar_init(mful + 8 * j, 1);     // completed by expect_tx + TMA
            mbar_init(memp + 8 * j, 4);     // 4 consumer-warp arrivals
        }
    }
    __syncthreads();                        // mbarriers visible to all

    if (t >= 128) {
        // ---------------- producer warp ----------------
        if (t == 128) {
            const u64t pol = mkpolicy_evict_first();
            int eph[NSLOT] = {1, 1, 1};     // first empty-wait passes
            for (int s = 0; s < NSTAGE; s++) {
                const int j = s % NSLOT;
                mbar_wait(memp + 8 * j, eph[j]);
                eph[j] ^= 1;
                const unsigned m = mful + 8 * j;
                mbar_expect(m, STAGE_BYTES);
                bulk_g2s_ef(smb + SMEM_W + j * 32768,
                            Wt + (size_t)(c * NR + r0 + s * RS) * (NI * NO),
                            32768, m, pol);
#pragma unroll
                for (int b = 0; b < NB; b++)
                    bulk_g2s_ef(smb + SMEM_X + j * 4096 + b * (RS * NI * 4),
                                x + (size_t)((b * NC + c) * NR + r0 + s * RS) * NI,
                                RS * NI * 4, m, pol);
            }
        }
        return;
    }

    // ---------------- consumer warps ----------------
    const int rj = t >> 6;
    const int bq = (t >> 4) & 3;
    const int og = t & 15;
    const int b0 = 2 * bq, b1 = 2 * bq + 1;
    const int lane0 = ((t & 31) == 0);

    int fph[NSLOT] = {0, 0, 0};
    float4 ms0 = make_float4(0.f, 0.f, 0.f, 0.f);
    float4 ms1 = make_float4(0.f, 0.f, 0.f, 0.f);

    for (int s = 0; s < NSTAGE; s++) {
        const int j = s % NSLOT;
        mbar_wait(mful + 8 * j, fph[j]);
        fph[j] ^= 1;

        const float*  Wb  = sW + j * (RS * NI * NO) + rj * (NI * NO);
        const float4* xr0 = (const float4*)(sX + j * (NB * RS * NI) + (b0 * RS + rj) * NI);
        const float4* xr1 = (const float4*)(sX + j * (NB * RS * NI) + (b1 * RS + rj) * NI);

        float4 a0 = make_float4(0.f, 0.f, 0.f, 0.f);
        float4 a1 = make_float4(0.f, 0.f, 0.f, 0.f);

#pragma unroll
        for (int i4 = 0; i4 < NI / 4; i4++) {
            float4 xv0 = xr0[i4];
            float4 xv1 = xr1[i4];
            const float4* wrow = (const float4*)(Wb + (i4 * 4) * NO) + og;
            float4 w0 = wrow[0];
            float4 w1 = wrow[16];
            float4 w2 = wrow[32];
            float4 w3 = wrow[48];
            FMA4(a0, xv0.x, w0); FMA4(a1, xv1.x, w0);
            FMA4(a0, xv0.y, w1); FMA4(a1, xv1.y, w1);
            FMA4(a0, xv0.z, w2); FMA4(a1, xv1.z, w2);
            FMA4(a0, xv0.w, w3); FMA4(a1, xv1.w, w3);
        }

        const int r = r0 + s * RS + rj;
        {
            union { uint2 u; __half2 h[2]; } pk;
            pk.h[0] = __floats2half2_rn(a0.x, a0.y);
            pk.h[1] = __floats2half2_rn(a0.z, a0.w);
            *(uint2*)(g_ph + (size_t)((b0 * NC + c) * NR + r) * NO + 4 * og) = pk.u;
            pk.h[0] = __floats2half2_rn(a1.x, a1.y);
            pk.h[1] = __floats2half2_rn(a1.z, a1.w);
            *(uint2*)(g_ph + (size_t)((b1 * NC + c) * NR + r) * NO + 4 * og) = pk.u;
        }

        ms0.x += a0.x; ms0.y += a0.y; ms0.z += a0.z; ms0.w += a0.w;
        ms1.x += a1.x; ms1.y += a1.y; ms1.z += a1.z; ms1.w += a1.w;

        __syncwarp();
        if (lane0) mbar_arrive(memp + 8 * j);   // this warp done with slot j
    }

    // iteration-0 fusion: sum_r priors -> g_pnum quarter 0
    float* d0 = g_pnum + (b0 * NC + c) * NO + 4 * og;
    float* d1 = g_pnum + (b1 * NC + c) * NO + 4 * og;
    atomicAdd(d0 + 0, ms0.x); atomicAdd(d0 + 1, ms0.y);
    atomicAdd(d0 + 2, ms0.z); atomicAdd(d0 + 3, ms0.w);
    atomicAdd(d1 + 0, ms1.x); atomicAdd(d1 + 1, ms1.y);
    atomicAdd(d1 + 2, ms1.z); atomicAdd(d1 + 3, ms1.w);
}

// ---------------------------------------------------------------------------
// Kernel 2: routing iteration + FUSED squash (last-block pattern).
// Each block: one bulk-TMA 64 KB quarter-slab -> smem, branch-free softmax
// partials from LDS, write quarter partials, bump counter. The LAST block
// combines quarters, computes the global squash scale, and updates g_w
// (last=0) or writes out (last=1). Counter self-resets for the next launch.
// ---------------------------------------------------------------------------
__global__ __launch_bounds__(512) void iter_kernel(float* __restrict__ out, int last)
{
    extern __shared__ float sm[];
    const __half* tile = (const __half*)sm;                 // 64 KB
    float* smr = sm + ITER_RED / 4;                         // [2][32][64]
    const unsigned smb = sptr(sm);
    const unsigned mb  = smb + ITER_MBAR;

    const int blk = blockIdx.x;
    const int bc  = blk >> 2;
    const int qq  = blk & 3;
    const int t   = threadIdx.x;
    const int o4  = t & 15;
    const int g   = t >> 4;

    if (t == 0) mbar_init(mb, 1);
    __syncthreads();
    if (t == 0) {
        mbar_expect(mb, ITER_TILE);
        bulk_g2s(smb, g_ph + (size_t)bc * NR * NO + (size_t)qq * (NR / NQ) * NO,
                 ITER_TILE, mb);
    }

    const float4 wv = ((const float4*)g_w)[bc * 16 + o4];

    mbar_wait(mb, 0);

    float d0 = 0.f, d1 = 0.f, d2 = 0.f, d3 = 0.f;
    float n0 = 0.f, n1 = 0.f, n2 = 0.f, n3 = 0.f;

#pragma unroll
    for (int k = 0; k < NR / NQ / 32; k++) {      // 16
        uint2 u = *(const uint2*)(tile + ((g + 32 * k) * NO + 4 * o4));
        float2 pa = __half22float2(*(__half2*)&u.x);
        float2 pb = __half22float2(*(__half2*)&u.y);
        float e;
        e = __expf(pa.x * wv.x); d0 += e; n0 += pa.x * e;
        e = __expf(pa.y * wv.y); d1 += e; n1 += pa.y * e;
        e = __expf(pb.x * wv.z); d2 += e; n2 += pb.x * e;
        e = __expf(pb.y * wv.w); d3 += e; n3 += pb.y * e;
    }

    {
        int ob = o4 * 4;
        float* sden = smr;              // [32][64]
        float* snum = smr + 32 * 64;
        sden[g * 64 + ob + 0] = d0; snum[g * 64 + ob + 0] = n0;
        sden[g * 64 + ob + 1] = d1; snum[g * 64 + ob + 1] = n1;
        sden[g * 64 + ob + 2] = d2; snum[g * 64 + ob + 2] = n2;
        sden[g * 64 + ob + 3] = d3; snum[g * 64 + ob + 3] = n3;
    }
    __syncthreads();

    if (t < 64) {
        float D = 0.f, N = 0.f;
        float* sden = smr;
        float* snum = smr + 32 * 64;
#pragma unroll 8
        for (int g2 = 0; g2 < 32; g2++) {
            D += sden[g2 * 64 + t];
            N += snum[g2 * 64 + t];
        }
        g_pden[qq * TOT + bc * NO + t] = D;
        g_pnum[qq * TOT + bc * NO + t] = N;
        __threadfence();                // release partials
    }
    __syncthreads();

    __shared__ int s_islast;
    if (t == 0) {
        int v = atomicAdd(&g_cnt, 1);
        s_islast = (v == (int)gridDim.x - 1);
    }
    __syncthreads();
    if (!s_islast) return;

    // ---------------- fused squash (last block only) ----------------
    if (t == 0) { g_cnt = 0; __threadfence(); }   // reset for next launch

    float sv[32];
    float acc = 0.f;
#pragma unroll
    for (int q = 0; q < 32; q++) {
        int j = t + 512 * q;
        float D = g_pden[j] + g_pden[TOT + j] + g_pden[2 * TOT + j] + g_pden[3 * TOT + j];
        float N = g_pnum[j] + g_pnum[TOT + j] + g_pnum[2 * TOT + j] + g_pnum[3 * TOT + j];
        float s = N / D;
        sv[q] = s;
        acc += s * s;
    }

    __shared__ float red[16];
    __shared__ float s_scale;
#pragma unroll
    for (int off = 16; off > 0; off >>= 1)
        acc += __shfl_xor_sync(0xFFFFFFFFu, acc, off);
    if ((t & 31) == 0) red[t >> 5] = acc;
    __syncthreads();
    if (t < 32) {
        float a = (t < 16) ? red[t] : 0.f;
#pragma unroll
        for (int off = 8; off > 0; off >>= 1)
            a += __shfl_xor_sync(0xFFFFFFFFu, a, off);
        if (t == 0) s_scale = sqrtf(a) / (1.0f + a);
    }
    __syncthreads();
    const float sc = s_scale;

    if (last) {
#pragma unroll
        for (int q = 0; q < 32; q++) out[t + 512 * q] = sv[q] * sc;
    } else {
#pragma unroll
        for (int q = 0; q < 32; q++) g_w[t + 512 * q] += sv[q] * sc;
    }
}

// ---------------------------------------------------------------------------
// Kernel 3: standalone squash for iteration 0 only (s = mean of priors).
// ---------------------------------------------------------------------------
__global__ __launch_bounds__(512) void squash0_kernel()
{
    const int t = threadIdx.x;

    float sv[32];
    float acc = 0.f;
#pragma unroll
    for (int q = 0; q < 32; q++) {
        int j = t + 512 * q;
        float s = g_pnum[j] * (1.0f / (float)NR);
        sv[q] = s;
        acc += s * s;
    }

    __shared__ float red[16];
    __shared__ float s_scale;
#pragma unroll
    for (int off = 16; off > 0; off >>= 1)
        acc += __shfl_xor_sync(0xFFFFFFFFu, acc, off);
    if ((t & 31) == 0) red[t >> 5] = acc;
    __syncthreads();
    if (t < 32) {
        float a = (t < 16) ? red[t] : 0.f;
#pragma unroll
        for (int off = 8; off > 0; off >>= 1)
            a += __shfl_xor_sync(0xFFFFFFFFu, a, off);
        if (t == 0) s_scale = sqrtf(a) / (1.0f + a);
    }
    __syncthreads();
    const float sc = s_scale;

#pragma unroll
    for (int q = 0; q < 32; q++) g_w[t + 512 * q] = sv[q] * sc;
}

// ---------------------------------------------------------------------------
extern "C" void kernel_launch(void* const* d_in, const int* in_sizes, int n_in,
                              void* d_out, int out_size)
{
    (void)in_sizes; (void)n_in; (void)out_size;
    const float* x  = (const float*)d_in[0];
    const float* Wt = (const float*)d_in[1];
    float* out = (float*)d_out;

    cudaFuncSetAttribute(priors_kernel,
                         cudaFuncAttributeMaxDynamicSharedMemorySize, SMEM_TOTAL);
    cudaFuncSetAttribute(iter_kernel,
                         cudaFuncAttributeMaxDynamicSharedMemorySize, ITER_SMEM);

    zero_kernel<<<32, 512>>>();
    priors_kernel<<<dim3(NR / RT, NC), 160, SMEM_TOTAL>>>(x, Wt);

    squash0_kernel<<<1, 512>>>();                              // w = v0

    iter_kernel<<<NQ * NB * NC, 512, ITER_SMEM>>>(nullptr, 0); // iter 1 + squash -> w
    iter_kernel<<<NQ * NB * NC, 512, ITER_SMEM>>>(out, 1);     // iter 2 + squash -> out
}

// round 14
// speedup vs baseline: 1.0470x; 1.0347x over previous
#include <cuda_runtime.h>
#include <cuda_fp16.h>
#include <cstdint>
#include <math.h>

#define NB 8
#define NC 32
#define NR 2048
#define NI 64
#define NO 64
#define RT 16                 // r-values per priors block
#define RS 2                  // r-values per pipeline stage (32 KB W slab)
#define NSTAGE (RT / RS)      // 8
#define NSLOT 3               // pipeline ring depth
#define NQ 4                  // R-split quarters in iter_kernel

// priors dynamic smem layout (bytes): W 3x32KB | x 3x4KB | mbar
#define SMEM_W     0
#define SMEM_X     98304
#define SMEM_MBAR  110592     // full[3] then empty[3], 8B each
#define SMEM_TOTAL 110656

#define STAGE_BYTES (32768 + 4096)

#define TOT (NB * NC * NO)    // 16384

// Scratch (static device globals — no allocation in kernel_launch)
__device__ __half g_ph[NB * NC * NR * NO];      // 67 MB fp16 priors
__device__ float  g_w[TOT];                     // cumulative v (logit weight)
__device__ float  g_pden[NQ * TOT];             // per-quarter softmax denominators
__device__ float  g_pnum[NQ * TOT];             // per-quarter numerators; [0] also = sum_r priors
__device__ int    g_cnt;                        // last-block counter (reset by last block)

typedef unsigned long long u64t;

// ---------------------------------------------------------------------------
__device__ __forceinline__ unsigned sptr(const void* p) {
    return (unsigned)__cvta_generic_to_shared(p);
}
__device__ __forceinline__ void mbar_init(unsigned m, unsigned cnt) {
    asm volatile("mbarrier.init.shared.b64 [%0], %1;" :: "r"(m), "r"(cnt) : "memory");
}
__device__ __forceinline__ void mbar_expect(unsigned m, unsigned bytes) {
    asm volatile("mbarrier.arrive.expect_tx.shared.b64 _, [%0], %1;"
                 :: "r"(m), "r"(bytes) : "memory");
}
__device__ __forceinline__ void mbar_arrive(unsigned m) {
    asm volatile("mbarrier.arrive.shared.b64 _, [%0];" :: "r"(m) : "memory");
}
__device__ __forceinline__ u64t mkpolicy_evict_first() {
    u64t p;
    asm("createpolicy.fractional.L2::evict_first.b64 %0, 1.0;" : "=l"(p));
    return p;
}
__device__ __forceinline__ void bulk_g2s_ef(unsigned dst, const void* src,
                                            unsigned bytes, unsigned m, u64t pol) {
    asm volatile("cp.async.bulk.shared::cta.global.mbarrier::complete_tx::bytes"
                 ".L2::cache_hint [%0], [%1], %2, [%3], %4;"
                 :: "r"(dst), "l"(src), "r"(bytes), "r"(m), "l"(pol) : "memory");
}
__device__ __forceinline__ void mbar_wait(unsigned m, unsigned ph) {
    asm volatile(
        "{\n\t.reg .pred P;\n\t"
        "W1_%=:\n\t"
        "mbarrier.try_wait.parity.acquire.cta.shared::cta.b64 P, [%0], %1, 0x989680;\n\t"
        "@P bra W2_%=;\n\t"
        "bra W1_%=;\n\t"
        "W2_%=:\n\t}"
        :: "r"(m), "r"(ph) : "memory");
}

#define FMA4(A, S, W) { (A).x += (S)*(W).x; (A).y += (S)*(W).y; \
                        (A).z += (S)*(W).z; (A).w += (S)*(W).w; }

// ---------------------------------------------------------------------------
// Kernel 0: zero the accumulators (g_w, quarter-0 of g_pnum, counter).
// ---------------------------------------------------------------------------
__global__ __launch_bounds__(512) void zero_kernel()
{
    int i = blockIdx.x * 512 + threadIdx.x;
    if (i < TOT) { g_w[i] = 0.0f; g_pnum[i] = 0.0f; }
    if (i == 0) g_cnt = 0;
}

// ---------------------------------------------------------------------------
// Kernel 1: priors (round-11 best config, verbatim). Warp-decoupled 3-slot
// TMA ring, evict-first on the W/x stream, iteration-0 sum fused via atomics.
// ---------------------------------------------------------------------------
__global__ __launch_bounds__(160) void priors_kernel(
    const float* __restrict__ x, const float* __restrict__ Wt)
{
    extern __shared__ float sm[];
    float* sW = sm;                          // [NSLOT][RS*NI*NO]
    float* sX = sm + SMEM_X / 4;             // [NSLOT][NB][RS*NI]
    const unsigned smb  = sptr(sm);
    const unsigned mful = smb + SMEM_MBAR;         // full[j] = mful + 8j
    const unsigned memp = smb + SMEM_MBAR + 24;    // empty[j] = memp + 8j

    const int c  = blockIdx.y;
    const int r0 = blockIdx.x * RT;
    const int t  = threadIdx.x;

    if (t == 0) {
#pragma unroll
        for (int j = 0; j < NSLOT; j++) {
            mbar_init(mful + 8 * j, 1);     // completed by expect_tx + TMA
            mbar_init(memp + 8 * j, 4);     // 4 consumer-warp arrivals
        }
    }
    __syncthreads();                        // mbarriers visible to all

    if (t >= 128) {
        // ---------------- producer warp ----------------
        if (t == 128) {
            const u64t pol = mkpolicy_evict_first();
            int eph[NSLOT] = {1, 1, 1};     // first empty-wait passes
            for (int s = 0; s < NSTAGE; s++) {
                const int j = s % NSLOT;
                mbar_wait(memp + 8 * j, eph[j]);
                eph[j] ^= 1;
                const unsigned m = mful + 8 * j;
                mbar_expect(m, STAGE_BYTES);
                bulk_g2s_ef(smb + SMEM_W + j * 32768,
                            Wt + (size_t)(c * NR + r0 + s * RS) * (NI * NO),
                            32768, m, pol);
#pragma unroll
                for (int b = 0; b < NB; b++)
                    bulk_g2s_ef(smb + SMEM_X + j * 4096 + b * (RS * NI * 4),
                                x + (size_t)((b * NC + c) * NR + r0 + s * RS) * NI,
                                RS * NI * 4, m, pol);
            }
        }
        return;
    }

    // ---------------- consumer warps ----------------
    const int rj = t >> 6;
    const int bq = (t >> 4) & 3;
    const int og = t & 15;
    const int b0 = 2 * bq, b1 = 2 * bq + 1;
    const int lane0 = ((t & 31) == 0);

    int fph[NSLOT] = {0, 0, 0};
    float4 ms0 = make_float4(0.f, 0.f, 0.f, 0.f);
    float4 ms1 = make_float4(0.f, 0.f, 0.f, 0.f);

    for (int s = 0; s < NSTAGE; s++) {
        const int j = s % NSLOT;
        mbar_wait(mful + 8 * j, fph[j]);
        fph[j] ^= 1;

        const float*  Wb  = sW + j * (RS * NI * NO) + rj * (NI * NO);
        const float4* xr0 = (const float4*)(sX + j * (NB * RS * NI) + (b0 * RS + rj) * NI);
        const float4* xr1 = (const float4*)(sX + j * (NB * RS * NI) + (b1 * RS + rj) * NI);

        float4 a0 = make_float4(0.f, 0.f, 0.f, 0.f);
        float4 a1 = make_float4(0.f, 0.f, 0.f, 0.f);

#pragma unroll
        for (int i4 = 0; i4 < NI / 4; i4++) {
            float4 xv0 = xr0[i4];
            float4 xv1 = xr1[i4];
            const float4* wrow = (const float4*)(Wb + (i4 * 4) * NO) + og;
            float4 w0 = wrow[0];
            float4 w1 = wrow[16];
            float4 w2 = wrow[32];
            float4 w3 = wrow[48];
            FMA4(a0, xv0.x, w0); FMA4(a1, xv1.x, w0);
            FMA4(a0, xv0.y, w1); FMA4(a1, xv1.y, w1);
            FMA4(a0, xv0.z, w2); FMA4(a1, xv1.z, w2);
            FMA4(a0, xv0.w, w3); FMA4(a1, xv1.w, w3);
        }

        const int r = r0 + s * RS + rj;
        {
            union { uint2 u; __half2 h[2]; } pk;
            pk.h[0] = __floats2half2_rn(a0.x, a0.y);
            pk.h[1] = __floats2half2_rn(a0.z, a0.w);
            *(uint2*)(g_ph + (size_t)((b0 * NC + c) * NR + r) * NO + 4 * og) = pk.u;
            pk.h[0] = __floats2half2_rn(a1.x, a1.y);
            pk.h[1] = __floats2half2_rn(a1.z, a1.w);
            *(uint2*)(g_ph + (size_t)((b1 * NC + c) * NR + r) * NO + 4 * og) = pk.u;
        }

        ms0.x += a0.x; ms0.y += a0.y; ms0.z += a0.z; ms0.w += a0.w;
        ms1.x += a1.x; ms1.y += a1.y; ms1.z += a1.z; ms1.w += a1.w;

        __syncwarp();
        if (lane0) mbar_arrive(memp + 8 * j);   // this warp done with slot j
    }

    // iteration-0 fusion: sum_r priors -> g_pnum quarter 0
    float* d0 = g_pnum + (b0 * NC + c) * NO + 4 * og;
    float* d1 = g_pnum + (b1 * NC + c) * NO + 4 * og;
    atomicAdd(d0 + 0, ms0.x); atomicAdd(d0 + 1, ms0.y);
    atomicAdd(d0 + 2, ms0.z); atomicAdd(d0 + 3, ms0.w);
    atomicAdd(d1 + 0, ms1.x); atomicAdd(d1 + 1, ms1.y);
    atomicAdd(d1 + 2, ms1.z); atomicAdd(d1 + 3, ms1.w);
}

// ---------------------------------------------------------------------------
// Kernel 2: routing iteration (round-11 direct-LDG body: 16 outstanding loads
// per thread, regs ~40, smem 16 KB) + FUSED squash via last-block pattern.
// Grid = NQ blocks per (b,c), 512 rows each. The LAST block combines quarter
// partials, computes the global squash scale, and updates g_w (last=0) or
// writes out (last=1). Counter self-resets for the next launch.
// ---------------------------------------------------------------------------
__global__ __launch_bounds__(512) void iter_kernel(float* __restrict__ out, int last)
{
    const int blk = blockIdx.x;
    const int bc  = blk >> 2;
    const int qq  = blk & 3;
    const int t   = threadIdx.x;
    const int o4  = t & 15;
    const int g   = t >> 4;

    const uint2* p2 = (const uint2*)(g_ph + (size_t)bc * NR * NO)
                      + (size_t)qq * (NR / NQ) * 16;
    const float4 wv = ((const float4*)g_w)[bc * 16 + o4];

    float d0 = 0.f, d1 = 0.f, d2 = 0.f, d3 = 0.f;
    float n0 = 0.f, n1 = 0.f, n2 = 0.f, n3 = 0.f;

#pragma unroll
    for (int k = 0; k < NR / NQ / 32; k++) {      // 16
        uint2 u = p2[(size_t)(g + 32 * k) * 16 + o4];
        float2 pa = __half22float2(*(__half2*)&u.x);
        float2 pb = __half22float2(*(__half2*)&u.y);
        float e;
        e = __expf(pa.x * wv.x); d0 += e; n0 += pa.x * e;
        e = __expf(pa.y * wv.y); d1 += e; n1 += pa.y * e;
        e = __expf(pb.x * wv.z); d2 += e; n2 += pb.x * e;
        e = __expf(pb.y * wv.w); d3 += e; n3 += pb.y * e;
    }

    __shared__ float smr[2][32][64];
    {
        int ob = o4 * 4;
        smr[0][g][ob + 0] = d0; smr[1][g][ob + 0] = n0;
        smr[0][g][ob + 1] = d1; smr[1][g][ob + 1] = n1;
        smr[0][g][ob + 2] = d2; smr[1][g][ob + 2] = n2;
        smr[0][g][ob + 3] = d3; smr[1][g][ob + 3] = n3;
    }
    __syncthreads();

    if (t < 64) {
        float D = 0.f, N = 0.f;
#pragma unroll 8
        for (int g2 = 0; g2 < 32; g2++) {
            D += smr[0][g2][t];
            N += smr[1][g2][t];
        }
        g_pden[qq * TOT + bc * NO + t] = D;
        g_pnum[qq * TOT + bc * NO + t] = N;
        __threadfence();                // release partials
    }
    __syncthreads();

    __shared__ int s_islast;
    if (t == 0) {
        int v = atomicAdd(&g_cnt, 1);
        s_islast = (v == (int)gridDim.x - 1);
    }
    __syncthreads();
    if (!s_islast) return;

    // ---------------- fused squash (last block only) ----------------
    if (t == 0) { g_cnt = 0; __threadfence(); }   // reset for next launch

    float sv[32];
    float acc = 0.f;
#pragma unroll
    for (int q = 0; q < 32; q++) {
        int j = t + 512 * q;
        float D = g_pden[j] + g_pden[TOT + j] + g_pden[2 * TOT + j] + g_pden[3 * TOT + j];
        float N = g_pnum[j] + g_pnum[TOT + j] + g_pnum[2 * TOT + j] + g_pnum[3 * TOT + j];
        float s = N / D;
        sv[q] = s;
        acc += s * s;
    }

    __shared__ float red[16];
    __shared__ float s_scale;
#pragma unroll
    for (int off = 16; off > 0; off >>= 1)
        acc += __shfl_xor_sync(0xFFFFFFFFu, acc, off);
    if ((t & 31) == 0) red[t >> 5] = acc;
    __syncthreads();
    if (t < 32) {
        float a = (t < 16) ? red[t] : 0.f;
#pragma unroll
        for (int off = 8; off > 0; off >>= 1)
            a += __shfl_xor_sync(0xFFFFFFFFu, a, off);
        if (t == 0) s_scale = sqrtf(a) / (1.0f + a);
    }
    __syncthreads();
    const float sc = s_scale;

    if (last) {
#pragma unroll
        for (int q = 0; q < 32; q++) out[t + 512 * q] = sv[q] * sc;
    } else {
#pragma unroll
        for (int q = 0; q < 32; q++) g_w[t + 512 * q] += sv[q] * sc;
    }
}

// ---------------------------------------------------------------------------
// Kernel 3: standalone squash for iteration 0 only (s = mean of priors).
// ---------------------------------------------------------------------------
__global__ __launch_bounds__(512) void squash0_kernel()
{
    const int t = threadIdx.x;

    float sv[32];
    float acc = 0.f;
#pragma unroll
    for (int q = 0; q < 32; q++) {
        int j = t + 512 * q;
        float s = g_pnum[j] * (1.0f / (float)NR);
        sv[q] = s;
        acc += s * s;
    }

    __shared__ float red[16];
    __shared__ float s_scale;
#pragma unroll
    for (int off = 16; off > 0; off >>= 1)
        acc += __shfl_xor_sync(0xFFFFFFFFu, acc, off);
    if ((t & 31) == 0) red[t >> 5] = acc;
    __syncthreads();
    if (t < 32) {
        float a = (t < 16) ? red[t] : 0.f;
#pragma unroll
        for (int off = 8; off > 0; off >>= 1)
            a += __shfl_xor_sync(0xFFFFFFFFu, a, off);
        if (t == 0) s_scale = sqrtf(a) / (1.0f + a);
    }
    __syncthreads();
    const float sc = s_scale;

#pragma unroll
    for (int q = 0; q < 32; q++) g_w[t + 512 * q] = sv[q] * sc;
}

// ---------------------------------------------------------------------------
extern "C" void kernel_launch(void* const* d_in, const int* in_sizes, int n_in,
                              void* d_out, int out_size)
{
    (void)in_sizes; (void)n_in; (void)out_size;
    const float* x  = (const float*)d_in[0];
    const float* Wt = (const float*)d_in[1];
    float* out = (float*)d_out;

    cudaFuncSetAttribute(priors_kernel,
                         cudaFuncAttributeMaxDynamicSharedMemorySize, SMEM_TOTAL);

    zero_kernel<<<32, 512>>>();
    priors_kernel<<<dim3(NR / RT, NC), 160, SMEM_TOTAL>>>(x, Wt);

    squash0_kernel<<<1, 512>>>();                       // w = v0

    iter_kernel<<<NQ * NB * NC, 512>>>(nullptr, 0);     // iter 1 + squash -> w
    iter_kernel<<<NQ * NB * NC, 512>>>(out, 1);         // iter 2 + squash -> out
}